// round 2
// baseline (speedup 1.0000x reference)
#include <cuda_runtime.h>
#include <cstdint>

#define HSZ   512
#define ISZ   256
#define BSZ   64
#define NBLK  128
#define NTHR  128
#define WH_STR 516   // 512 + 4 pad (bank-conflict-free LDS.128 across rows)
#define WI_STR 260   // 256 + 4 pad
#define EPSBN 1e-5f

// smem layout (floats)
#define OFF_WH   0
#define OFF_WI   (OFF_WH + 16*WH_STR)          // 8256
#define OFF_ST   (OFF_WI + 16*WI_STR)          // +4160
#define OFF_SG   (OFF_ST + 2*4096)             // +8192
#define OFF_CST  (OFF_SG + 16*64)              // +1024
#define SMEM_FLOATS (OFF_CST + 96)
#define SMEM_BYTES  (SMEM_FLOATS*4)

__device__ float g_h[2][HSZ*BSZ];              // double-buffered hidden state
__device__ unsigned g_arrive;
__device__ unsigned g_release;

__device__ __forceinline__ unsigned long long pack2(float lo, float hi){
    unsigned long long r;
    asm("mov.b64 %0, {%1, %2};" : "=l"(r) : "f"(lo), "f"(hi));
    return r;
}
__device__ __forceinline__ void unpack2(unsigned long long v, float &lo, float &hi){
    asm("mov.b64 {%0, %1}, %2;" : "=f"(lo), "=f"(hi) : "l"(v));
}
__device__ __forceinline__ void ffma2(unsigned long long &acc, unsigned long long a, unsigned long long b){
    asm("fma.rn.f32x2 %0, %1, %2, %0;" : "+l"(acc) : "l"(a), "l"(b));
}
__device__ __forceinline__ void cp16(uint32_t dst, const void* src){
    asm volatile("cp.async.cg.shared.global [%0], [%1], 16;" :: "r"(dst), "l"(src));
}
__device__ __forceinline__ float sigm(float x){
    return 1.0f / (1.0f + __expf(-x));
}

// one 64-k-slice of GEMM: thread does 2 rows x 4 cols (cols as 2 f32x2 pairs)
__device__ __forceinline__ void gemm_chunk(const float* __restrict__ st,
                                           const float* __restrict__ w0,
                                           const float* __restrict__ w1,
                                           int c0,
                                           unsigned long long &a00, unsigned long long &a01,
                                           unsigned long long &a10, unsigned long long &a11)
{
    #pragma unroll
    for (int kk = 0; kk < 64; kk += 4){
        float4 wa = *(const float4*)(w0 + kk);
        float4 wb = *(const float4*)(w1 + kk);
        ulonglong2 h0 = *(const ulonglong2*)(st + (kk+0)*64 + c0);
        ulonglong2 h1 = *(const ulonglong2*)(st + (kk+1)*64 + c0);
        ulonglong2 h2 = *(const ulonglong2*)(st + (kk+2)*64 + c0);
        ulonglong2 h3 = *(const ulonglong2*)(st + (kk+3)*64 + c0);
        unsigned long long s;
        s = pack2(wa.x, wa.x); ffma2(a00, s, h0.x); ffma2(a01, s, h0.y);
        s = pack2(wb.x, wb.x); ffma2(a10, s, h0.x); ffma2(a11, s, h0.y);
        s = pack2(wa.y, wa.y); ffma2(a00, s, h1.x); ffma2(a01, s, h1.y);
        s = pack2(wb.y, wb.y); ffma2(a10, s, h1.x); ffma2(a11, s, h1.y);
        s = pack2(wa.z, wa.z); ffma2(a00, s, h2.x); ffma2(a01, s, h2.y);
        s = pack2(wb.z, wb.z); ffma2(a10, s, h2.x); ffma2(a11, s, h2.y);
        s = pack2(wa.w, wa.w); ffma2(a00, s, h3.x); ffma2(a01, s, h3.y);
        s = pack2(wb.w, wb.w); ffma2(a10, s, h3.x); ffma2(a11, s, h3.y);
    }
}

extern "C" __global__ void __launch_bounds__(NTHR, 1)
lstm_bn_kernel(const float* __restrict__ x,
               const float* __restrict__ Wih,
               const float* __restrict__ Whh,
               const float* __restrict__ bias,
               const float* __restrict__ gIH, const float* __restrict__ bIH,
               const float* __restrict__ gHH, const float* __restrict__ bHH,
               const float* __restrict__ gC,  const float* __restrict__ bC,
               float* __restrict__ out, int T)
{
    extern __shared__ float sm[];
    float* wh_s   = sm + OFF_WH;
    float* wi_s   = sm + OFF_WI;
    float* stage  = sm + OFF_ST;
    float* sg     = sm + OFF_SG;
    float* ghh_s  = sm + OFF_CST;       // 16
    float* bhh_s  = ghh_s + 16;
    float* gih_s  = bhh_s + 16;
    float* bih_s  = gih_s + 16;
    float* bias_s = bih_s + 16;
    float* gc_s   = bias_s + 16;        // 4
    float* bc_s   = gc_s + 4;           // 4

    const int tid = threadIdx.x;
    const int blk = blockIdx.x;
    const int ct  = tid & 15;
    const int rt  = tid >> 4;
    const int c0  = ct * 4;
    const int l0  = rt * 2;

    // ---- preload weight slices (block owns 16 gate rows: l = q*4 + j -> row q*512 + blk*4 + j)
    #pragma unroll
    for (int l = 0; l < 16; l++){
        int grow = (l >> 2) * HSZ + blk*4 + (l & 3);
        ((float4*)(wh_s + l*WH_STR))[tid] = ((const float4*)(Whh + (size_t)grow * HSZ))[tid];
        if (tid < 64)
            ((float4*)(wi_s + l*WI_STR))[tid] = ((const float4*)(Wih + (size_t)grow * ISZ))[tid];
    }
    if (tid < 16){
        int grow = (tid >> 2) * HSZ + blk*4 + (tid & 3);
        ghh_s[tid] = gHH[grow]; bhh_s[tid] = bHH[grow];
        gih_s[tid] = gIH[grow]; bih_s[tid] = bIH[grow];
        bias_s[tid] = bias[grow];
    }
    if (tid < 4){ gc_s[tid] = gC[blk*4 + tid]; bc_s[tid] = bC[blk*4 + tid]; }

    // ---- zero h buffer 0 (this block's slice: 256 floats)
    {
        int base = blk * ((HSZ*BSZ) / NBLK);
        g_h[0][base + tid]       = 0.f;
        g_h[0][base + tid + 128] = 0.f;
    }
    __syncthreads();

    unsigned gen0 = 0, my_gen = 0;
    if (tid == 0) gen0 = *((volatile unsigned*)&g_release);

    auto gridsync = [&](){
        __syncthreads();
        if (tid == 0){
            my_gen++;
            __threadfence();
            unsigned a = atomicAdd(&g_arrive, 1u);
            if (a == (unsigned)(NBLK - 1)){
                atomicExch(&g_arrive, 0u);
                __threadfence();
                atomicAdd(&g_release, 1u);
            } else {
                while ( (*((volatile unsigned*)&g_release)) - gen0 < my_gen ) { }
            }
        }
        __syncthreads();
    };

    gridsync();   // h buffer zeroed everywhere before step 0

    const uint32_t stBase = (uint32_t)__cvta_generic_to_shared(stage);
    const float inv64 = 1.0f / 64.0f;
    float creg0 = 0.f, creg1 = 0.f;     // cell state, block-local rows forever
    const int wwarp = tid >> 5;         // 0..3 -> local h-row
    const int lane  = tid & 31;

    for (int t = 0; t < T; t++){
        const float* hrd = g_h[t & 1];
        float*       hwr = g_h[(t + 1) & 1];
        const float* xt  = x + (size_t)t * (ISZ*BSZ);

        unsigned long long aA00=0, aA01=0, aA10=0, aA11=0;  // W_hh @ h
        unsigned long long aB00=0, aB01=0, aB10=0, aB11=0;  // W_ih @ x_t

        // prefetch chunk 0 (hh, k=0..63)
        {
            uint32_t d = stBase;
            #pragma unroll
            for (int i = 0; i < 8; i++)
                cp16(d + (tid + i*128)*16, hrd + (tid + i*128)*4);
            asm volatile("cp.async.commit_group;");
        }

        for (int ci = 0; ci < 12; ci++){
            if (ci < 11){
                int cn = ci + 1;
                const float* src = (cn < 8) ? (hrd + cn*4096) : (xt + (cn - 8)*4096);
                uint32_t d = stBase + (uint32_t)((cn & 1) * 4096) * 4u;
                #pragma unroll
                for (int i = 0; i < 8; i++)
                    cp16(d + (tid + i*128)*16, src + (tid + i*128)*4);
                asm volatile("cp.async.commit_group;");
                asm volatile("cp.async.wait_group 1;");
            } else {
                asm volatile("cp.async.wait_group 0;");
            }
            __syncthreads();

            const float* st = stage + (ci & 1) * 4096;
            if (ci < 8){
                const float* w0 = wh_s + l0*WH_STR + ci*64;
                gemm_chunk(st, w0, w0 + WH_STR, c0, aA00, aA01, aA10, aA11);
            } else {
                const float* w0 = wi_s + l0*WI_STR + (ci - 8)*64;
                gemm_chunk(st, w0, w0 + WI_STR, c0, aB00, aB01, aB10, aB11);
            }
            __syncthreads();   // protect staging buffer before next prefetch overwrites
        }

        // ---- phase A: per-gate-row batchnorm (rows spread over 16 lanes of half-warp)
        float vA0[4], vA1[4], vB0[4], vB1[4];
        unpack2(aA00, vA0[0], vA0[1]); unpack2(aA01, vA0[2], vA0[3]);
        unpack2(aA10, vA1[0], vA1[1]); unpack2(aA11, vA1[2], vA1[3]);
        unpack2(aB00, vB0[0], vB0[1]); unpack2(aB01, vB0[2], vB0[3]);
        unpack2(aB10, vB1[0], vB1[1]); unpack2(aB11, vB1[2], vB1[3]);

        #pragma unroll
        for (int r = 0; r < 2; r++){
            float* vA = r ? vA1 : vA0;
            float* vB = r ? vB1 : vB0;
            const int l = l0 + r;
            float sA = vA[0]+vA[1]+vA[2]+vA[3];
            float qA = vA[0]*vA[0]+vA[1]*vA[1]+vA[2]*vA[2]+vA[3]*vA[3];
            float sB = vB[0]+vB[1]+vB[2]+vB[3];
            float qB = vB[0]*vB[0]+vB[1]*vB[1]+vB[2]*vB[2]+vB[3]*vB[3];
            #pragma unroll
            for (int off = 1; off < 16; off <<= 1){
                sA += __shfl_xor_sync(0xffffffffu, sA, off);
                qA += __shfl_xor_sync(0xffffffffu, qA, off);
                sB += __shfl_xor_sync(0xffffffffu, sB, off);
                qB += __shfl_xor_sync(0xffffffffu, qB, off);
            }
            float muA = sA*inv64, muB = sB*inv64;
            float rsA = rsqrtf(qA*inv64 - muA*muA + EPSBN);
            float rsB = rsqrtf(qB*inv64 - muB*muB + EPSBN);
            float ga = ghh_s[l]*rsA, gb = gih_s[l]*rsB;
            float cadd = bhh_s[l] + bih_s[l] + bias_s[l] - muA*ga - muB*gb;
            #pragma unroll
            for (int j = 0; j < 4; j++)
                sg[l*64 + c0 + j] = fmaf(vA[j], ga, fmaf(vB[j], gb, cadd));
        }
        __syncthreads();

        // ---- phase B: gates + cell update + c-batchnorm + h (warp w owns h-row blk*4+w)
        {
            float iv0 = sg[( 0 + wwarp)*64 + lane], iv1 = sg[( 0 + wwarp)*64 + lane + 32];
            float fv0 = sg[( 4 + wwarp)*64 + lane], fv1 = sg[( 4 + wwarp)*64 + lane + 32];
            float gv0 = sg[( 8 + wwarp)*64 + lane], gv1 = sg[( 8 + wwarp)*64 + lane + 32];
            float ov0 = sg[(12 + wwarp)*64 + lane], ov1 = sg[(12 + wwarp)*64 + lane + 32];

            creg0 = sigm(fv0)*creg0 + sigm(iv0)*tanhf(gv0);
            creg1 = sigm(fv1)*creg1 + sigm(iv1)*tanhf(gv1);

            float sc = creg0 + creg1;
            float qc = creg0*creg0 + creg1*creg1;
            #pragma unroll
            for (int off = 16; off >= 1; off >>= 1){
                sc += __shfl_xor_sync(0xffffffffu, sc, off);
                qc += __shfl_xor_sync(0xffffffffu, qc, off);
            }
            float mu = sc*inv64;
            float rs = rsqrtf(qc*inv64 - mu*mu + EPSBN);
            float gcv = gc_s[wwarp]*rs;
            float bcv = bc_s[wwarp] - mu*gcv;
            float h0v = sigm(ov0) * tanhf(fmaf(creg0, gcv, bcv));
            float h1v = sigm(ov1) * tanhf(fmaf(creg1, gcv, bcv));

            int rowg = blk*4 + wwarp;
            hwr[rowg*64 + lane]      = h0v;
            hwr[rowg*64 + lane + 32] = h1v;
            float* op = out + (size_t)t * (HSZ*BSZ) + rowg*64;
            op[lane]      = h0v;
            op[lane + 32] = h1v;
        }

        gridsync();   // h visible chip-wide before next step's loads
    }
}

extern "C" void kernel_launch(void* const* d_in, const int* in_sizes, int n_in,
                              void* d_out, int out_size)
{
    const float* x    = (const float*)d_in[0];
    const float* Wih  = (const float*)d_in[1];
    const float* Whh  = (const float*)d_in[2];
    const float* bias = (const float*)d_in[3];
    const float* gIH  = (const float*)d_in[4];
    const float* bIH  = (const float*)d_in[5];
    const float* gHH  = (const float*)d_in[6];
    const float* bHH  = (const float*)d_in[7];
    const float* gC   = (const float*)d_in[8];
    const float* bC   = (const float*)d_in[9];
    float* out = (float*)d_out;

    int T = in_sizes[0] / (ISZ * BSZ);   // 2048

    cudaFuncSetAttribute(lstm_bn_kernel,
                         cudaFuncAttributeMaxDynamicSharedMemorySize, SMEM_BYTES);
    lstm_bn_kernel<<<NBLK, NTHR, SMEM_BYTES>>>(x, Wih, Whh, bias,
                                               gIH, bIH, gHH, bHH, gC, bC,
                                               out, T);
}